// round 4
// baseline (speedup 1.0000x reference)
#include <cuda_runtime.h>
#include <math.h>

#define T_DIM 512
#define B_DIM 1024
#define V_DIM 96
#define L_DIM 48
#define S_DIM 97   // 2L+1

// scratch (no cudaMalloc allowed)
__device__ float g_lse[T_DIM * B_DIM];
__device__ float g_loss[B_DIM];

// ---------------------------------------------------------------------------
// Kernel A: lse[t*B+b] = logsumexp over V of y_pred[t,b,:]
// One warp per (t,b) row; V=96 -> 3 values per lane.
// ---------------------------------------------------------------------------
__global__ void __launch_bounds__(256) lse_kernel(const float* __restrict__ y_pred) {
    int warp = (blockIdx.x * blockDim.x + threadIdx.x) >> 5;
    int lane = threadIdx.x & 31;
    if (warp >= T_DIM * B_DIM) return;
    const float* row = y_pred + (size_t)warp * V_DIM;
    float x0 = row[lane];
    float x1 = row[lane + 32];
    float x2 = row[lane + 64];
    float m = fmaxf(x0, fmaxf(x1, x2));
    #pragma unroll
    for (int o = 16; o; o >>= 1) m = fmaxf(m, __shfl_xor_sync(0xFFFFFFFFu, m, o));
    float s = __expf(x0 - m) + __expf(x1 - m) + __expf(x2 - m);
    #pragma unroll
    for (int o = 16; o; o >>= 1) s += __shfl_xor_sync(0xFFFFFFFFu, s, o);
    if (lane == 0) g_lse[warp] = m + __logf(s);
}

// ---------------------------------------------------------------------------
// Kernel B: CTC forward recursion, linear-probability domain in FP64.
// One block per batch element, thread s owns extended-label state s (s<97).
// alpha'[s] = (alpha[s] + alpha[s-1] + skip*alpha[s-2]) * softmax_p[ext[s]]
// Exact power-of-2 rescale every 32 steps, max re-centered at 2^440.
// FP64 range (e^+-709, no FTZ) keeps >500 nats of tail window below the max,
// so no reachable path mass is ever flushed.
// ---------------------------------------------------------------------------
__global__ void __launch_bounds__(128) ctc_forward(const float* __restrict__ y_pred,
                                                   const int*   __restrict__ y_true) {
    const int b = blockIdx.x;
    const int s = threadIdx.x;
    const bool active = (s < S_DIM);

    __shared__ double sh_a[2][S_DIM + 3];
    __shared__ double red[4];

    // extended label id for this state; skip-transition predicate
    int e = 0;
    bool skip = false;
    if (active && (s & 1)) {
        e = y_true[b * L_DIM + ((s - 1) >> 1)];
        if (s >= 3) skip = (e != y_true[b * L_DIM + ((s - 3) >> 1)]);
    }

    const float* xbase = y_pred + (size_t)b * V_DIM + e;
    const size_t stride = (size_t)B_DIM * V_DIM;

    // t = 0, plus prefetch of t = 1
    float x    = active ? xbase[0] : 0.f;
    float lse  = g_lse[b];
    float xn   = active ? xbase[stride] : 0.f;
    float lsen = g_lse[B_DIM + b];

    int acc_k = 0;  // total power-of-2 shift applied to stored alphas
    double p0 = (double)__expf(x - lse);
    if (active) sh_a[0][s] = (s < 2) ? p0 : 0.0;
    __syncthreads();

    int cur = 0;
    for (int t = 1; t < T_DIM; t++) {
        x = xn; lse = lsen;
        if (t + 1 < T_DIM) {   // prefetch next timestep (static addresses)
            xn   = active ? xbase[(size_t)(t + 1) * stride] : 0.f;
            lsen = g_lse[(t + 1) * B_DIM + b];
        }
        float pf = __expf(x - lse);

        double a0 = 0.0, a1 = 0.0, a2 = 0.0;
        if (active) {
            a0 = sh_a[cur][s];
            a1 = (s >= 1) ? sh_a[cur][s - 1] : 0.0;
            a2 = skip ? sh_a[cur][s - 2] : 0.0;
        }
        double an = (a0 + a1 + a2) * (double)pf;

        const int nxt = cur ^ 1;
        if ((t & 31) == 31) {
            // block max of an -> rescale by exact power of two, recenter at 2^440
            double v = an;
            #pragma unroll
            for (int o = 16; o; o >>= 1) v = fmax(v, __shfl_xor_sync(0xFFFFFFFFu, v, o));
            if ((threadIdx.x & 31) == 0) red[threadIdx.x >> 5] = v;
            __syncthreads();
            double m = fmax(fmax(red[0], red[1]), fmax(red[2], red[3]));
            int eb = (__double2hiint(m) >> 20) & 0x7FF;
            int shift = (1023 + 440) - eb;     // multiply by 2^shift
            if (shift >  1020) shift =  1020;  // keep scale representable
            if (shift < -1020) shift = -1020;
            double scale = __hiloint2double((1023 + shift) << 20, 0);
            an *= scale;
            acc_k += shift;
        }
        if (active) sh_a[nxt][s] = an;
        __syncthreads();
        cur = nxt;
    }

    if (s == 0) {
        // true_alpha = stored_alpha * 2^{-acc_k}
        double fin = sh_a[cur][S_DIM - 1] + sh_a[cur][S_DIM - 2];
        double loss = -(log(fin) - (double)acc_k * 0.6931471805599453094);
        g_loss[b] = (float)loss;
    }
}

// ---------------------------------------------------------------------------
// Kernel C: deterministic mean over B losses -> scalar out
// ---------------------------------------------------------------------------
__global__ void __launch_bounds__(256) mean_kernel(float* __restrict__ out) {
    __shared__ float sh[256];
    int tid = threadIdx.x;
    float s = 0.f;
    for (int i = tid; i < B_DIM; i += 256) s += g_loss[i];
    sh[tid] = s;
    __syncthreads();
    #pragma unroll
    for (int o = 128; o; o >>= 1) {
        if (tid < o) sh[tid] += sh[tid + o];
        __syncthreads();
    }
    if (tid == 0) out[0] = sh[0] * (1.0f / (float)B_DIM);
}

extern "C" void kernel_launch(void* const* d_in, const int* in_sizes, int n_in,
                              void* d_out, int out_size) {
    const int*   y_true;
    const float* y_pred;
    // pick by size for robustness: y_true has B*L = 49152 elements
    if (in_sizes[0] == B_DIM * L_DIM) {
        y_true = (const int*)d_in[0];
        y_pred = (const float*)d_in[1];
    } else {
        y_true = (const int*)d_in[1];
        y_pred = (const float*)d_in[0];
    }

    // A: per-(t,b) logsumexp.  524288 rows, 1 warp each, 8 warps/block
    lse_kernel<<<(T_DIM * B_DIM) / 8, 256>>>(y_pred);
    // B: forward recursion, one block per batch element
    ctc_forward<<<B_DIM, 128>>>(y_pred, y_true);
    // C: mean
    mean_kernel<<<1, 256>>>((float*)d_out);
}

// round 5
// speedup vs baseline: 1.0987x; 1.0987x over previous
#include <cuda_runtime.h>
#include <math.h>
#include <float.h>

#define T_DIM 512
#define B_DIM 1024
#define V_DIM 96
#define L_DIM 48
#define S_DIM 97   // 2L+1

// scratch (no cudaMalloc allowed)
__device__ float g_lse[T_DIM * B_DIM];
__device__ float g_loss[B_DIM];

// ---------------------------------------------------------------------------
// Kernel A: lse[row] = logsumexp over V of y_pred row (row = t*B+b).
// One warp per 2 rows (row w and w + nrows/2), float4 loads (24 lanes active),
// two independent reduction chains for ILP / MLP.
// ---------------------------------------------------------------------------
__global__ void __launch_bounds__(256) lse_kernel(const float* __restrict__ y_pred) {
    const int NROWS = T_DIM * B_DIM;
    const int HALF  = NROWS / 2;
    int w    = (blockIdx.x * blockDim.x + threadIdx.x) >> 5;  // 0..HALF-1
    int lane = threadIdx.x & 31;
    if (w >= HALF) return;

    const float4* r0 = (const float4*)(y_pred + (size_t)w * V_DIM);
    const float4* r1 = (const float4*)(y_pred + (size_t)(w + HALF) * V_DIM);

    float4 a = (lane < 24) ? r0[lane] : make_float4(-FLT_MAX, -FLT_MAX, -FLT_MAX, -FLT_MAX);
    float4 c = (lane < 24) ? r1[lane] : make_float4(-FLT_MAX, -FLT_MAX, -FLT_MAX, -FLT_MAX);

    float ma = fmaxf(fmaxf(a.x, a.y), fmaxf(a.z, a.w));
    float mc = fmaxf(fmaxf(c.x, c.y), fmaxf(c.z, c.w));
    #pragma unroll
    for (int o = 16; o; o >>= 1) {
        ma = fmaxf(ma, __shfl_xor_sync(0xFFFFFFFFu, ma, o));
        mc = fmaxf(mc, __shfl_xor_sync(0xFFFFFFFFu, mc, o));
    }
    float sa = 0.f, sc = 0.f;
    if (lane < 24) {
        sa = __expf(a.x - ma) + __expf(a.y - ma) + __expf(a.z - ma) + __expf(a.w - ma);
        sc = __expf(c.x - mc) + __expf(c.y - mc) + __expf(c.z - mc) + __expf(c.w - mc);
    }
    #pragma unroll
    for (int o = 16; o; o >>= 1) {
        sa += __shfl_xor_sync(0xFFFFFFFFu, sa, o);
        sc += __shfl_xor_sync(0xFFFFFFFFu, sc, o);
    }
    if (lane == 0) {
        g_lse[w]        = ma + __logf(sa);
        g_lse[w + HALF] = mc + __logf(sc);
    }
}

// ---------------------------------------------------------------------------
// Kernel B: CTC forward recursion, linear-probability domain in FP64.
// One block per batch element, thread s owns extended-label state s (s<97).
// alpha'[s] = (alpha[s] + alpha[s-1] + skip*alpha[s-2]) * softmax_p[ext[s]]
// Depth-4 register prefetch queue for x and lse (addresses are static and
// alpha-independent) so DRAM latency is off the serial critical path.
// Exact power-of-2 rescale every 32 steps, max re-centered at 2^440.
// ---------------------------------------------------------------------------
#define PF 4
__global__ void __launch_bounds__(128) ctc_forward(const float* __restrict__ y_pred,
                                                   const int*   __restrict__ y_true) {
    const int b = blockIdx.x;
    const int s = threadIdx.x;
    const bool active = (s < S_DIM);

    __shared__ double sh_a[2][S_DIM + 3];
    __shared__ double red[4];

    // extended label id for this state; skip-transition predicate
    int e = 0;
    bool skip = false;
    if (active && (s & 1)) {
        e = y_true[b * L_DIM + ((s - 1) >> 1)];
        if (s >= 3) skip = (e != y_true[b * L_DIM + ((s - 3) >> 1)]);
    }

    const float* xbase = y_pred + (size_t)b * V_DIM + e;
    const size_t stride = (size_t)B_DIM * V_DIM;

    // t = 0
    float x0  = active ? xbase[0] : 0.f;
    float ls0 = g_lse[b];

    // prefetch queue for t = 1..PF
    float xq[PF], lq[PF];
    #pragma unroll
    for (int j = 0; j < PF; j++) {
        int tt = 1 + j;
        xq[j] = active ? xbase[(size_t)tt * stride] : 0.f;
        lq[j] = g_lse[tt * B_DIM + b];
    }

    int acc_k = 0;  // total power-of-2 shift applied to stored alphas
    double p0 = (double)__expf(x0 - ls0);
    if (active) sh_a[0][s] = (s < 2) ? p0 : 0.0;
    __syncthreads();

    int cur = 0;
    #pragma unroll 4
    for (int t = 1; t < T_DIM; t++) {
        const int slot = (t - 1) & (PF - 1);
        float x = xq[slot], lse = lq[slot];
        const int tp = t + PF;
        if (tp < T_DIM) {   // refill queue slot, consumed PF iterations later
            xq[slot] = active ? xbase[(size_t)tp * stride] : 0.f;
            lq[slot] = g_lse[tp * B_DIM + b];
        }
        double pd = (double)__expf(x - lse);   // off the alpha critical path

        double a0 = 0.0, a1 = 0.0, a2 = 0.0;
        if (active) {
            a0 = sh_a[cur][s];
            a1 = (s >= 1) ? sh_a[cur][s - 1] : 0.0;
            a2 = skip ? sh_a[cur][s - 2] : 0.0;
        }
        double an = ((a0 + a1) + a2) * pd;

        const int nxt = cur ^ 1;
        if ((t & 31) == 31) {
            // block max of an -> rescale by exact power of two, recenter at 2^440
            double v = an;
            #pragma unroll
            for (int o = 16; o; o >>= 1) v = fmax(v, __shfl_xor_sync(0xFFFFFFFFu, v, o));
            if ((threadIdx.x & 31) == 0) red[threadIdx.x >> 5] = v;
            __syncthreads();
            double m = fmax(fmax(red[0], red[1]), fmax(red[2], red[3]));
            int eb = (__double2hiint(m) >> 20) & 0x7FF;
            int shift = (1023 + 440) - eb;     // multiply by 2^shift
            if (shift >  1020) shift =  1020;
            if (shift < -1020) shift = -1020;
            double scale = __hiloint2double((1023 + shift) << 20, 0);
            an *= scale;
            acc_k += shift;
        }
        if (active) sh_a[nxt][s] = an;
        __syncthreads();
        cur = nxt;
    }

    if (s == 0) {
        // true_alpha = stored_alpha * 2^{-acc_k}
        double fin = sh_a[cur][S_DIM - 1] + sh_a[cur][S_DIM - 2];
        double loss = -(log(fin) - (double)acc_k * 0.6931471805599453094);
        g_loss[b] = (float)loss;
    }
}

// ---------------------------------------------------------------------------
// Kernel C: deterministic mean over B losses -> scalar out
// ---------------------------------------------------------------------------
__global__ void __launch_bounds__(256) mean_kernel(float* __restrict__ out) {
    __shared__ float sh[256];
    int tid = threadIdx.x;
    float s = 0.f;
    for (int i = tid; i < B_DIM; i += 256) s += g_loss[i];
    sh[tid] = s;
    __syncthreads();
    #pragma unroll
    for (int o = 128; o; o >>= 1) {
        if (tid < o) sh[tid] += sh[tid + o];
        __syncthreads();
    }
    if (tid == 0) out[0] = sh[0] * (1.0f / (float)B_DIM);
}

extern "C" void kernel_launch(void* const* d_in, const int* in_sizes, int n_in,
                              void* d_out, int out_size) {
    const int*   y_true;
    const float* y_pred;
    // pick by size for robustness: y_true has B*L = 49152 elements
    if (in_sizes[0] == B_DIM * L_DIM) {
        y_true = (const int*)d_in[0];
        y_pred = (const float*)d_in[1];
    } else {
        y_true = (const int*)d_in[1];
        y_pred = (const float*)d_in[0];
    }

    // A: per-(t,b) logsumexp. 262144 warps x 2 rows, 8 warps/block
    lse_kernel<<<(T_DIM * B_DIM / 2) / 8, 256>>>(y_pred);
    // B: forward recursion, one block per batch element
    ctc_forward<<<B_DIM, 128>>>(y_pred, y_true);
    // C: mean
    mean_kernel<<<1, 256>>>((float*)d_out);
}

// round 6
// speedup vs baseline: 1.2598x; 1.1466x over previous
#include <cuda_runtime.h>
#include <math.h>
#include <float.h>

#define T_DIM 512
#define B_DIM 1024
#define V_DIM 96
#define L_DIM 48
#define S_DIM 97   // 2L+1

// scratch (no cudaMalloc allowed)
__device__ float  g_lse[T_DIM * B_DIM];
__device__ float  g_loss[B_DIM];     // "raw" loss: -log(alpha_unnorm_final)
__device__ double g_part[1024];      // per-block partial sums of lse

// ---------------------------------------------------------------------------
// Kernel A: lse[row] = logsumexp over V of y_pred row (row = t*B+b).
// 4 rows per warp, 8 lanes per row, 3x float4 per lane (12 elems).
// Intra-8-lane-group butterfly reductions (offsets 4,2,1).
// ---------------------------------------------------------------------------
__global__ void __launch_bounds__(256) lse_kernel(const float* __restrict__ y_pred) {
    int warp = (blockIdx.x * blockDim.x + threadIdx.x) >> 5;
    int lane = threadIdx.x & 31;
    int g = lane >> 3, sub = lane & 7;
    int row = warp * 4 + g;                       // grid sized exactly

    const float* p = y_pred + (size_t)row * V_DIM + sub * 4;
    float4 v0 = *(const float4*)(p);
    float4 v1 = *(const float4*)(p + 32);
    float4 v2 = *(const float4*)(p + 64);

    float m = fmaxf(fmaxf(fmaxf(v0.x, v0.y), fmaxf(v0.z, v0.w)),
             fmaxf(fmaxf(fmaxf(v1.x, v1.y), fmaxf(v1.z, v1.w)),
                   fmaxf(fmaxf(v2.x, v2.y), fmaxf(v2.z, v2.w))));
    #pragma unroll
    for (int o = 4; o; o >>= 1) m = fmaxf(m, __shfl_xor_sync(0xFFFFFFFFu, m, o));

    float s = __expf(v0.x - m) + __expf(v0.y - m) + __expf(v0.z - m) + __expf(v0.w - m)
            + __expf(v1.x - m) + __expf(v1.y - m) + __expf(v1.z - m) + __expf(v1.w - m)
            + __expf(v2.x - m) + __expf(v2.y - m) + __expf(v2.z - m) + __expf(v2.w - m);
    #pragma unroll
    for (int o = 4; o; o >>= 1) s += __shfl_xor_sync(0xFFFFFFFFu, s, o);

    if (sub == 0) g_lse[row] = m + __logf(s);
}

// ---------------------------------------------------------------------------
// Kernel B: CTC forward recursion on UNNORMALIZED probabilities exp(x).
// The softmax denominator exp(-lse) is state-uniform, so it factors out of
// the linear recursion; it is re-added at the end via sum_t lse (kernels C1/C2).
//
// One WARP per batch element. Lane l owns states 4l..4l+3 in registers:
//   even states (blank): n = (a[s] + a[s-1]) * pb
//   odd  states        : n = (a[s] + a[s-1] + skip*a[s-2]) * p_label
// Only cross-lane term: prev lane's a3, via one __shfl_up per step.
// No shared memory, no __syncthreads. FP64 alphas; exact power-of-2 rescale
// every 16 steps (warp-local shfl reduction). Depth-4 register prefetch queue
// for the 3 per-step gathers keeps DRAM latency off the serial chain.
// ---------------------------------------------------------------------------
#define PF 4
__global__ void __launch_bounds__(128) ctc_forward(const float* __restrict__ y_pred,
                                                   const int*   __restrict__ y_true) {
    const int b = (blockIdx.x * blockDim.x + threadIdx.x) >> 5;   // warp id = batch
    const int l = threadIdx.x & 31;

    // labels 2l and 2l+1 for this lane (l < 24); safe zeros otherwise
    int lab0 = 0, lab1 = 0;
    if (l < 24) {
        int2 lp = *(const int2*)(y_true + b * L_DIM + 2 * l);
        lab0 = lp.x; lab1 = lp.y;
    }
    int prevlab1 = __shfl_up_sync(0xFFFFFFFFu, lab1, 1);
    const double skip1d = (l >= 1 && l < 24 && lab0 != prevlab1) ? 1.0 : 0.0;
    const double skip3d = (l < 24 && lab1 != lab0) ? 1.0 : 0.0;

    const float* xb_ptr = y_pred + (size_t)b * V_DIM;
    const size_t stride = (size_t)B_DIM * V_DIM;

    // t = 0: only states 0 (blank) and 1 (first label) alive, both on lane 0
    double a0 = 0.0, a1 = 0.0, a2 = 0.0, a3 = 0.0;
    {
        float xb0 = xb_ptr[0];
        float x00 = xb_ptr[lab0];
        if (l == 0) {
            a0 = (double)__expf(xb0);
            a1 = (double)__expf(x00);
        }
    }

    // prefetch queue for t = 1..PF
    float qb[PF], q0[PF], q1[PF];
    #pragma unroll
    for (int j = 0; j < PF; j++) {
        const float* xt = xb_ptr + (size_t)(1 + j) * stride;
        qb[j] = xt[0]; q0[j] = xt[lab0]; q1[j] = xt[lab1];
    }

    int acc_k = 0;   // power-of-2 shift applied to stored alphas
    for (int tb = 1; tb < T_DIM; tb += PF) {
        #pragma unroll
        for (int j = 0; j < PF; j++) {
            const int t = tb + j;
            float xb = qb[j], x0 = q0[j], x1 = q1[j];
            if (t + PF < T_DIM) {                       // refill, used PF later
                const float* xt = xb_ptr + (size_t)(t + PF) * stride;
                qb[j] = xt[0]; q0[j] = xt[lab0]; q1[j] = xt[lab1];
            }
            double pbd = (double)__expf(xb);            // off the alpha chain
            double p0d = (double)__expf(x0);
            double p1d = (double)__expf(x1);

            double sh3 = __shfl_up_sync(0xFFFFFFFFu, a3, 1);
            if (l == 0) sh3 = 0.0;

            double n0 = (a0 + sh3) * pbd;                      // s=4l   (blank)
            double n1 = (a0 + a1 + skip1d * sh3) * p0d;        // s=4l+1 (label 2l)
            double n2 = (a1 + a2) * pbd;                       // s=4l+2 (blank)
            double n3 = (a2 + a3 + skip3d * a1) * p1d;         // s=4l+3 (label 2l+1)
            if (l >= 24) { n1 = 0.0; n2 = 0.0; n3 = 0.0; }     // states >= 97
            if (l >  24) { n0 = 0.0; }
            a0 = n0; a1 = n1; a2 = n2; a3 = n3;

            if ((t & 15) == 15) {
                // warp max -> exact power-of-2 recenter to 2^0
                double v = fmax(fmax(a0, a1), fmax(a2, a3));
                #pragma unroll
                for (int o = 16; o; o >>= 1)
                    v = fmax(v, __shfl_xor_sync(0xFFFFFFFFu, v, o));
                int eb = (__double2hiint(v) >> 20) & 0x7FF;
                int shift = 1023 - eb;
                if (shift >  1020) shift =  1020;
                if (shift < -1020) shift = -1020;
                double scale = __hiloint2double((1023 + shift) << 20, 0);
                a0 *= scale; a1 *= scale; a2 *= scale; a3 *= scale;
                acc_k += shift;
            }
        }
    }

    // terminal states: s=95 (lane 23, a3) and s=96 (lane 24, a0)
    double v95 = __shfl_sync(0xFFFFFFFFu, a3, 23);
    double v96 = __shfl_sync(0xFFFFFFFFu, a0, 24);
    if (l == 0) {
        // alpha_unnorm = stored * 2^{-acc_k};  raw = -log(alpha_unnorm)
        g_loss[b] = (float)(-log(v95 + v96) + (double)acc_k * 0.6931471805599453094);
    }
}

// ---------------------------------------------------------------------------
// Kernel C1: partial sums of all T*B lse values (1024 blocks x 512 elems)
// ---------------------------------------------------------------------------
__global__ void __launch_bounds__(256) lse_part_kernel() {
    __shared__ double sh[256];
    int tid = threadIdx.x;
    size_t base = (size_t)blockIdx.x * 512;
    double s = (double)g_lse[base + tid] + (double)g_lse[base + tid + 256];
    sh[tid] = s;
    __syncthreads();
    #pragma unroll
    for (int o = 128; o; o >>= 1) {
        if (tid < o) sh[tid] += sh[tid + o];
        __syncthreads();
    }
    if (tid == 0) g_part[blockIdx.x] = sh[0];
}

// ---------------------------------------------------------------------------
// Kernel C2: mean_loss = (sum_b raw_b + sum_{t,b} lse) / B
// ---------------------------------------------------------------------------
__global__ void __launch_bounds__(256) final_kernel(float* __restrict__ out) {
    __shared__ double sh[256];
    int tid = threadIdx.x;
    double s = 0.0;
    #pragma unroll
    for (int i = tid; i < 1024; i += 256) s += g_part[i] + (double)g_loss[i];
    sh[tid] = s;
    __syncthreads();
    #pragma unroll
    for (int o = 128; o; o >>= 1) {
        if (tid < o) sh[tid] += sh[tid + o];
        __syncthreads();
    }
    if (tid == 0) out[0] = (float)(sh[0] * (1.0 / (double)B_DIM));
}

extern "C" void kernel_launch(void* const* d_in, const int* in_sizes, int n_in,
                              void* d_out, int out_size) {
    const int*   y_true;
    const float* y_pred;
    // pick by size for robustness: y_true has B*L = 49152 elements
    if (in_sizes[0] == B_DIM * L_DIM) {
        y_true = (const int*)d_in[0];
        y_pred = (const float*)d_in[1];
    } else {
        y_true = (const int*)d_in[1];
        y_pred = (const float*)d_in[0];
    }

    // A: per-(t,b) logsumexp. 131072 warps x 4 rows, 8 warps/block
    lse_kernel<<<(T_DIM * B_DIM / 4) / 8, 256>>>(y_pred);
    // B: forward recursion, one warp per batch element (no barriers, no smem)
    ctc_forward<<<B_DIM / 4, 128>>>(y_pred, y_true);
    // C1/C2: fold sum of lse back in, produce mean
    lse_part_kernel<<<1024, 256>>>();
    final_kernel<<<1, 256>>>((float*)d_out);
}